// round 2
// baseline (speedup 1.0000x reference)
#include <cuda_runtime.h>
#include <math.h>

// Problem constants
#define HDIM 4096
#define MSTK 104
#define GEMV_BLOCKS 256              // 16 rows per block, 2 rows per warp

// Inter-kernel scratch for h (no allocation allowed; static device array)
__device__ float g_h[HDIM];

// ---------------------------------------------------------------------------
// Kernel 1: h = tanh(W_ih @ emb + b_ih + W_hh @ hbar + b_hh)
//   emb  = E[inp[0]]            (row of E, length 4096)
//   hbar = W_sh[:,0]*stack[0] + b_sh + hidden0
// Grid: 256 blocks x 256 threads. Each block: 16 rows, 8 warps, 2 rows/warp.
// ---------------------------------------------------------------------------
__global__ __launch_bounds__(256, 2)
void k_hidden(const int* __restrict__ inp,
              const float* __restrict__ hidden0,
              const float* __restrict__ stack,
              const float* __restrict__ E,
              const float* __restrict__ W_ih,
              const float* __restrict__ b_ih,
              const float* __restrict__ W_hh,
              const float* __restrict__ b_hh,
              const float* __restrict__ W_sh,
              const float* __restrict__ b_sh,
              float* __restrict__ out_hidden)   // d_out + 4096
{
    __shared__ float s_emb[HDIM];
    __shared__ float s_hbar[HDIM];

    const int tid = threadIdx.x;
    const int erow = inp[0];
    const float s0 = stack[0];

    const float4* __restrict__ E4   = (const float4*)(E + (size_t)erow * HDIM);
    const float4* __restrict__ Wsh4 = (const float4*)W_sh;
    const float4* __restrict__ bsh4 = (const float4*)b_sh;
    const float4* __restrict__ h04  = (const float4*)hidden0;

    for (int i = tid; i < HDIM / 4; i += blockDim.x) {
        ((float4*)s_emb)[i] = E4[i];
        float4 ws = Wsh4[i];
        float4 bs = bsh4[i];
        float4 h0 = h04[i];
        float4 hb;
        hb.x = fmaf(ws.x, s0, bs.x) + h0.x;
        hb.y = fmaf(ws.y, s0, bs.y) + h0.y;
        hb.z = fmaf(ws.z, s0, bs.z) + h0.z;
        hb.w = fmaf(ws.w, s0, bs.w) + h0.w;
        ((float4*)s_hbar)[i] = hb;
    }
    __syncthreads();

    const int warp = tid >> 5;
    const int lane = tid & 31;
    const int base_row = blockIdx.x * 16 + warp * 2;

    #pragma unroll
    for (int r = 0; r < 2; r++) {
        const int row = base_row + r;
        const float4* __restrict__ wi = (const float4*)(W_ih + (size_t)row * HDIM);
        const float4* __restrict__ wh = (const float4*)(W_hh + (size_t)row * HDIM);
        float acc = 0.0f;
        #pragma unroll 4
        for (int k = lane; k < HDIM / 4; k += 32) {
            float4 a  = wi[k];
            float4 b  = wh[k];
            float4 e  = ((const float4*)s_emb)[k];
            float4 hb = ((const float4*)s_hbar)[k];
            acc = fmaf(a.x, e.x, acc);
            acc = fmaf(a.y, e.y, acc);
            acc = fmaf(a.z, e.z, acc);
            acc = fmaf(a.w, e.w, acc);
            acc = fmaf(b.x, hb.x, acc);
            acc = fmaf(b.y, hb.y, acc);
            acc = fmaf(b.z, hb.z, acc);
            acc = fmaf(b.w, hb.w, acc);
        }
        #pragma unroll
        for (int o = 16; o > 0; o >>= 1)
            acc += __shfl_down_sync(0xFFFFFFFFu, acc, o);
        if (lane == 0) {
            float hv = tanhf(acc + b_ih[row] + b_hh[row]);
            g_h[row] = hv;
            out_hidden[row] = hv;   // hidden output = h
        }
    }
}

// ---------------------------------------------------------------------------
// Kernel 2:
//   blocks 0..GEMV_BLOCKS-1 : output = sigmoid(W_y @ h + b_y)  -> out[0:4096]
//   block GEMV_BLOCKS       : aw = softmax(W_a @ h + b_a)
//                             new_elt = sigmoid(W_n @ h + b_n)
//                             new_stack = aw0*push + aw1*pop   -> out[8192:8296]
//                             weights = aw0 + aw1              -> out[8296]
// ---------------------------------------------------------------------------
__global__ __launch_bounds__(256, 2)
void k_out(const float* __restrict__ W_y,
           const float* __restrict__ b_y,
           const float* __restrict__ W_n,
           const float* __restrict__ b_n,
           const float* __restrict__ W_a,
           const float* __restrict__ b_a,
           const float* __restrict__ stack,
           float* __restrict__ out)
{
    __shared__ float s_h[HDIM];
    __shared__ float red[3][8];
    __shared__ float s_small[3];   // aw0, aw1, new_elt

    const int tid = threadIdx.x;
    for (int i = tid; i < HDIM; i += blockDim.x) s_h[i] = g_h[i];
    __syncthreads();

    const int warp = tid >> 5;
    const int lane = tid & 31;

    if (blockIdx.x < GEMV_BLOCKS) {
        const int base_row = blockIdx.x * 16 + warp * 2;
        #pragma unroll
        for (int r = 0; r < 2; r++) {
            const int row = base_row + r;
            const float4* __restrict__ wy = (const float4*)(W_y + (size_t)row * HDIM);
            float acc = 0.0f;
            #pragma unroll 4
            for (int k = lane; k < HDIM / 4; k += 32) {
                float4 a  = wy[k];
                float4 h4 = ((const float4*)s_h)[k];
                acc = fmaf(a.x, h4.x, acc);
                acc = fmaf(a.y, h4.y, acc);
                acc = fmaf(a.z, h4.z, acc);
                acc = fmaf(a.w, h4.w, acc);
            }
            #pragma unroll
            for (int o = 16; o > 0; o >>= 1)
                acc += __shfl_down_sync(0xFFFFFFFFu, acc, o);
            if (lane == 0) {
                float z = acc + b_y[row];
                out[row] = 1.0f / (1.0f + expf(-z));   // sigmoid
            }
        }
    } else {
        // --- small block: W_a (2xH), W_n (1xH), softmax, stack blend ---
        float p0 = 0.0f, p1 = 0.0f, pn = 0.0f;
        for (int i = tid; i < HDIM; i += blockDim.x) {
            float hv = s_h[i];
            p0 = fmaf(W_a[i],        hv, p0);
            p1 = fmaf(W_a[HDIM + i], hv, p1);
            pn = fmaf(W_n[i],        hv, pn);
        }
        #pragma unroll
        for (int o = 16; o > 0; o >>= 1) {
            p0 += __shfl_down_sync(0xFFFFFFFFu, p0, o);
            p1 += __shfl_down_sync(0xFFFFFFFFu, p1, o);
            pn += __shfl_down_sync(0xFFFFFFFFu, pn, o);
        }
        if (lane == 0) { red[0][warp] = p0; red[1][warp] = p1; red[2][warp] = pn; }
        __syncthreads();
        if (tid == 0) {
            float z0 = b_a[0], z1 = b_a[1], zn = b_n[0];
            #pragma unroll
            for (int w = 0; w < 8; w++) { z0 += red[0][w]; z1 += red[1][w]; zn += red[2][w]; }
            float m  = fmaxf(z0, z1);
            float e0 = expf(z0 - m);
            float e1 = expf(z1 - m);
            float inv = 1.0f / (e0 + e1);
            float aw0 = e0 * inv;
            float aw1 = e1 * inv;
            s_small[0] = aw0;
            s_small[1] = aw1;
            s_small[2] = 1.0f / (1.0f + expf(-zn));    // new_elt
            out[8296] = aw0 + aw1;                      // weights
        }
        __syncthreads();
        const float aw0 = s_small[0];
        const float aw1 = s_small[1];
        const float ne  = s_small[2];
        if (tid < MSTK) {
            float push = (tid == 0)        ? ne : stack[tid - 1];
            float pop  = (tid < MSTK - 1)  ? stack[tid + 1] : 0.0f;
            out[8192 + tid] = fmaf(aw0, push, aw1 * pop);
        }
    }
}

// ---------------------------------------------------------------------------
// kernel_launch
// Input order (metadata): 0 inp(i32), 1 hidden0, 2 stack, 3 E, 4 W_ih, 5 b_ih,
//   6 W_hh, 7 b_hh, 8 W_y, 9 b_y, 10 W_n, 11 b_n, 12 W_a, 13 b_a, 14 W_sh, 15 b_sh
// Output layout (fp32, 8297): [0:4096) output, [4096:8192) hidden,
//   [8192:8296) new_stack, [8296] weights
// ---------------------------------------------------------------------------
extern "C" void kernel_launch(void* const* d_in, const int* in_sizes, int n_in,
                              void* d_out, int out_size)
{
    const int*   inp     = (const int*)  d_in[0];
    const float* hidden0 = (const float*)d_in[1];
    const float* stack   = (const float*)d_in[2];
    const float* E       = (const float*)d_in[3];
    const float* W_ih    = (const float*)d_in[4];
    const float* b_ih    = (const float*)d_in[5];
    const float* W_hh    = (const float*)d_in[6];
    const float* b_hh    = (const float*)d_in[7];
    const float* W_y     = (const float*)d_in[8];
    const float* b_y     = (const float*)d_in[9];
    const float* W_n     = (const float*)d_in[10];
    const float* b_n     = (const float*)d_in[11];
    const float* W_a     = (const float*)d_in[12];
    const float* b_a     = (const float*)d_in[13];
    const float* W_sh    = (const float*)d_in[14];
    const float* b_sh    = (const float*)d_in[15];

    float* out = (float*)d_out;

    k_hidden<<<GEMV_BLOCKS, 256>>>(inp, hidden0, stack, E, W_ih, b_ih, W_hh, b_hh,
                                   W_sh, b_sh, out + 4096);
    k_out<<<GEMV_BLOCKS + 1, 256>>>(W_y, b_y, W_n, b_n, W_a, b_a, stack, out);
}